// round 14
// baseline (speedup 1.0000x reference)
#include <cuda_runtime.h>
#include <cuda_bf16.h>
#include <cstdint>
#include <cstddef>

// Shapes (fixed): x [4, 256, 64, 64] fp32 ; HW=4096 ; 4 heads x d=64 ; 8 groups
#define BATCH 4
#define CC    256
#define HW    4096
#define NH    4
#define DH    64
#define NGRP  8

__device__ __nv_bfloat16 g_hb[BATCH * CC * HW];         // group-normed input (bf16)
__device__ __nv_bfloat16 g_qkvh[BATCH * 3 * CC * HW];   // qkv projection (bf16)
__device__ __nv_bfloat16 g_ob[BATCH * CC * HW];         // attention output (bf16)
__device__ __nv_bfloat16 g_qkvwT[CC * 3 * CC];          // qkv_w^T bf16 [k][m]
__device__ __nv_bfloat16 g_projwT[CC * CC];             // proj_w^T bf16 [k][m]

// ---------------------------------------------------------------------------
// helpers
// ---------------------------------------------------------------------------
__device__ __forceinline__ void mma_bf16(float* d, const uint32_t* a,
                                         uint32_t b0, uint32_t b1) {
    asm volatile(
        "mma.sync.aligned.m16n8k16.row.col.f32.bf16.bf16.f32 "
        "{%0,%1,%2,%3}, {%4,%5,%6,%7}, {%8,%9}, {%0,%1,%2,%3};\n"
        : "+f"(d[0]), "+f"(d[1]), "+f"(d[2]), "+f"(d[3])
        : "r"(a[0]), "r"(a[1]), "r"(a[2]), "r"(a[3]), "r"(b0), "r"(b1));
}

__device__ __forceinline__ void ldsm4(uint32_t& r0, uint32_t& r1, uint32_t& r2,
                                      uint32_t& r3, uint32_t addr) {
    asm volatile("ldmatrix.sync.aligned.m8n8.x4.shared.b16 {%0,%1,%2,%3}, [%4];"
                 : "=r"(r0), "=r"(r1), "=r"(r2), "=r"(r3) : "r"(addr));
}

__device__ __forceinline__ void ldsm4t(uint32_t& r0, uint32_t& r1, uint32_t& r2,
                                       uint32_t& r3, uint32_t addr) {
    asm volatile("ldmatrix.sync.aligned.m8n8.x4.trans.shared.b16 {%0,%1,%2,%3}, [%4];"
                 : "=r"(r0), "=r"(r1), "=r"(r2), "=r"(r3) : "r"(addr));
}

__device__ __forceinline__ uint32_t pk_bf16(float lo, float hi) {
    uint32_t r;
    asm("cvt.rn.bf16x2.f32 %0, %1, %2;" : "=r"(r) : "f"(hi), "f"(lo));
    return r;
}

__device__ __forceinline__ float ex2(float x) {
    float r;
    asm("ex2.approx.ftz.f32 %0, %1;" : "=f"(r) : "f"(x));
    return r;
}

__device__ __forceinline__ uint32_t sptr(const void* p) {
    return (uint32_t)__cvta_generic_to_shared(p);
}

__device__ __forceinline__ void cpa16(uint32_t saddr, const void* g) {
    asm volatile("cp.async.cg.shared.global [%0], [%1], 16;" :: "r"(saddr), "l"(g));
}
__device__ __forceinline__ void cpa_commit() {
    asm volatile("cp.async.commit_group;");
}
template <int N> __device__ __forceinline__ void cpa_wait() {
    asm volatile("cp.async.wait_group %0;" :: "n"(N));
}

// ---------------------------------------------------------------------------
// Kernel 0: weight convert+transpose: W[m][k] f32 -> W^T[k][m] bf16
// ---------------------------------------------------------------------------
__global__ void wconv_kernel(const float* __restrict__ qw, const float* __restrict__ pw) {
    const int idx = blockIdx.x * blockDim.x + threadIdx.x;   // 768*256 range
    {
        const int m = idx >> 8, k = idx & 255;
        g_qkvwT[k * 768 + m] = __float2bfloat16(qw[idx]);
    }
    if (idx < 256 * 256) {
        const int m = idx >> 8, k = idx & 255;
        g_projwT[k * 256 + m] = __float2bfloat16(pw[idx]);
    }
}

// ---------------------------------------------------------------------------
// Kernel 1: GroupNorm -> bf16. One CTA per (batch, group).
// ---------------------------------------------------------------------------
__global__ void gn_kernel(const float* __restrict__ x, const float* __restrict__ w,
                          const float* __restrict__ b) {
    const int bg = blockIdx.x;
    const int bb = bg >> 3, g = bg & 7;
    const size_t off = ((size_t)bb * CC + (size_t)g * 32) * HW;
    const float* xp = x + off;
    __nv_bfloat16* hp = g_hb + off;

    float s = 0.f, ss = 0.f;
    for (int i = threadIdx.x; i < 32 * HW; i += blockDim.x) {
        float v = xp[i]; s += v; ss += v * v;
    }
    #pragma unroll
    for (int o = 16; o; o >>= 1) {
        s  += __shfl_xor_sync(0xffffffffu, s, o);
        ss += __shfl_xor_sync(0xffffffffu, ss, o);
    }
    __shared__ float sh_s[16], sh_ss[16];
    __shared__ float sh_mean, sh_rstd;
    const int wid = threadIdx.x >> 5, lid = threadIdx.x & 31;
    if (lid == 0) { sh_s[wid] = s; sh_ss[wid] = ss; }
    __syncthreads();
    if (threadIdx.x == 0) {
        float t = 0.f, tt = 0.f;
        const int nw = blockDim.x >> 5;
        for (int i = 0; i < nw; i++) { t += sh_s[i]; tt += sh_ss[i]; }
        const float inv = 1.f / (32.f * HW);
        float mean = t * inv;
        float var = tt * inv - mean * mean;
        sh_mean = mean;
        sh_rstd = rsqrtf(var + 1e-5f);
    }
    __syncthreads();
    const float mean = sh_mean, rstd = sh_rstd;
    for (int idx = threadIdx.x; idx < 16 * HW; idx += blockDim.x) {
        const int i = idx * 2;
        const int c = g * 32 + (i >> 12);
        const float sc = rstd * w[c];
        float2 t = *(const float2*)(xp + i);
        *(uint32_t*)(hp + i) = pk_bf16((t.x - mean) * sc + b[c],
                                       (t.y - mean) * sc + b[c]);
    }
}

// ---------------------------------------------------------------------------
// Kernel 2/4: bf16 tensor-core GEMM, 64m x 256n CTA tile (4 n-subtiles reuse
// each A fragment -> 9:16 LDSM:mma, 4x compute per pipeline fill).
// cp.async double-buffered, K=256 (4 k-tiles).
// ---------------------------------------------------------------------------
#define GA_STR 72     // As row stride (bf16): [k][m]
#define GB_STR 264    // Bs row stride (bf16): [k][n], 33*8 -> conflict-free ldsm
#define GEMM_SMEM_BYTES ((2 * 64 * GA_STR + 2 * 64 * GB_STR) * 2)   // 86016

__global__ void __launch_bounds__(256) gemm_bf16_kernel(
        const __nv_bfloat16* __restrict__ WT, const __nv_bfloat16* __restrict__ X,
        const float* __restrict__ bias, const float* __restrict__ resid,
        float* __restrict__ Y, __nv_bfloat16* __restrict__ Ybf,
        int Mdim, long xBatch, long yBatch) {
    extern __shared__ __nv_bfloat16 gsm[];
    __nv_bfloat16* As0 = gsm;
    __nv_bfloat16* As1 = As0 + 64 * GA_STR;
    __nv_bfloat16* Bs0 = As1 + 64 * GA_STR;
    __nv_bfloat16* Bs1 = Bs0 + 64 * GB_STR;

    const int n0 = blockIdx.x * 256, m0 = blockIdx.y * 64, bb = blockIdx.z;
    const __nv_bfloat16* Xb = X + (size_t)bb * xBatch;

    const int tid = threadIdx.x;
    const int warp = tid >> 5, lane = tid & 31;
    const int gid = lane >> 2, tig = lane & 3;
    const int quad = lane >> 3, qr = lane & 7;
    const int wm = (warp >> 1) * 16, wn = (warp & 1) * 32;

    auto issue = [&](int k0, __nv_bfloat16* A, __nv_bfloat16* B) {
        #pragma unroll
        for (int t = 0; t < 2; t++) {
            const int idx = tid + t * 256;
            const int row = idx >> 3, blk = (idx & 7) * 8;
            cpa16(sptr(A + row * GA_STR + blk), WT + (size_t)(k0 + row) * Mdim + m0 + blk);
        }
        #pragma unroll
        for (int t = 0; t < 8; t++) {
            const int idx = tid + t * 256;
            const int row = idx >> 5, blk = (idx & 31) * 8;
            cpa16(sptr(B + row * GB_STR + blk), Xb + (size_t)(k0 + row) * HW + n0 + blk);
        }
    };

    float acc[16][4] = {};   // [sub*4 + nt][4]

    issue(0, As0, Bs0);
    cpa_commit();

    #pragma unroll
    for (int kt = 0; kt < 4; kt++) {
        __nv_bfloat16* Ac = (kt & 1) ? As1 : As0;
        __nv_bfloat16* Bc = (kt & 1) ? Bs1 : Bs0;
        if (kt < 3) issue((kt + 1) * 64, (kt & 1) ? As0 : As1, (kt & 1) ? Bs0 : Bs1);
        cpa_commit();
        cpa_wait<1>();
        __syncthreads();

        #pragma unroll
        for (int kc = 0; kc < 4; kc++) {
            uint32_t qa[4];
            ldsm4t(qa[0], qa[1], qa[2], qa[3],
                   sptr(&Ac[(kc * 16 + (quad >> 1) * 8 + qr) * GA_STR
                            + wm + (quad & 1) * 8]));
            #pragma unroll
            for (int sub = 0; sub < 4; sub++) {
                #pragma unroll
                for (int jp = 0; jp < 2; jp++) {
                    uint32_t b0, b1, b2, b3;
                    ldsm4t(b0, b1, b2, b3,
                           sptr(&Bc[(kc * 16 + (quad & 1) * 8 + qr) * GB_STR
                                    + sub * 64 + wn + jp * 16 + (quad >> 1) * 8]));
                    mma_bf16(acc[sub * 4 + 2 * jp],     qa, b0, b1);
                    mma_bf16(acc[sub * 4 + 2 * jp + 1], qa, b2, b3);
                }
            }
        }
        __syncthreads();
    }

    const int mr0 = m0 + wm + gid;
    const float b0 = bias[mr0], b1 = bias[mr0 + 8];
    #pragma unroll
    for (int sub = 0; sub < 4; sub++) {
        #pragma unroll
        for (int nt = 0; nt < 4; nt++) {
            float* a = acc[sub * 4 + nt];
            const int col = n0 + sub * 64 + wn + nt * 8 + 2 * tig;
            const size_t i0 = (size_t)bb * yBatch + (size_t)mr0 * HW + col;
            const size_t i1 = (size_t)bb * yBatch + (size_t)(mr0 + 8) * HW + col;
            if (Ybf) {
                *(uint32_t*)(Ybf + i0) = pk_bf16(a[0] + b0, a[1] + b0);
                *(uint32_t*)(Ybf + i1) = pk_bf16(a[2] + b1, a[3] + b1);
            } else {
                float2 r0 = make_float2(a[0] + b0, a[1] + b0);
                float2 r1 = make_float2(a[2] + b1, a[3] + b1);
                float2 x0 = *(const float2*)(resid + i0);
                float2 x1 = *(const float2*)(resid + i1);
                r0.x += x0.x; r0.y += x0.y; r1.x += x1.x; r1.y += x1.y;
                *(float2*)(Y + i0) = r0;
                *(float2*)(Y + i1) = r1;
            }
        }
    }
}

// ---------------------------------------------------------------------------
// Kernel 3: flash attention (Round-12 version: double-buffered K/V, full-tile
// phases). Fixed-shift softmax: p = 2^(s*SALPHA - MHAT); shift cancels in O/l.
// ---------------------------------------------------------------------------
#define QS_STR 136
#define KS_STR 72
#define ATTN_SMEM_BYTES ((8704 + 2 * 4608 + 2 * 4608) * 2)   // 54272
#define SALPHA 0.18033688011112042f   // 0.125 * log2(e)
#define MHAT   10.0f                  // fixed exp2-domain shift

__global__ void __launch_bounds__(256, 2) attn_kernel(
        const __nv_bfloat16* __restrict__ qkv, __nv_bfloat16* __restrict__ o) {
    extern __shared__ __nv_bfloat16 smb[];
    __nv_bfloat16* Qs = smb;                    // [64][136]
    __nv_bfloat16* Ks0 = smb + 8704;            // [64][72]
    __nv_bfloat16* Ks1 = Ks0 + 4608;
    __nv_bfloat16* Vs0 = Ks1 + 4608;
    __nv_bfloat16* Vs1 = Vs0 + 4608;

    const int bh = blockIdx.y, b = bh >> 2, hd = bh & 3;
    const int i0 = blockIdx.x * 128;
    const size_t base = (size_t)b * 3 * CC * HW;
    const __nv_bfloat16* q = qkv + base + (size_t)(hd * DH) * HW;
    const __nv_bfloat16* k = qkv + base + (size_t)(CC + hd * DH) * HW;
    const __nv_bfloat16* v = qkv + base + (size_t)(2 * CC + hd * DH) * HW;

    const int tid  = threadIdx.x;
    const int warp = tid >> 5, lane = tid & 31;
    const int gid = lane >> 2, tig = lane & 3;
    const int wm = warp * 16;
    const int quad = lane >> 3, qr = lane & 7;

    const int fr0 = tid >> 3,          fc0 = (tid & 7) * 8;
    const int fr1 = (tid + 256) >> 3,  fc1 = fc0;

    #pragma unroll
    for (int t = 0; t < 4; t++) {
        const int idx = tid + t * 256;
        const int c = idx >> 4, i8 = (idx & 15) * 8;
        cpa16(sptr(Qs + c * QS_STR + i8), q + (size_t)c * HW + i0 + i8);
    }
    cpa_commit();
    cpa16(sptr(Ks0 + fr0 * KS_STR + fc0), k + (size_t)fr0 * HW + fc0);
    cpa16(sptr(Ks0 + fr1 * KS_STR + fc1), k + (size_t)fr1 * HW + fc1);
    cpa16(sptr(Vs0 + fr0 * KS_STR + fc0), v + (size_t)fr0 * HW + fc0);
    cpa16(sptr(Vs0 + fr1 * KS_STR + fc1), v + (size_t)fr1 * HW + fc1);
    cpa_commit();

    cpa_wait<1>();
    __syncthreads();

    uint32_t qa[4][4];
    #pragma unroll
    for (int kc = 0; kc < 4; kc++) {
        const int c = kc * 16 + (quad >> 1) * 8 + qr;
        const int i = wm + (quad & 1) * 8;
        ldsm4t(qa[kc][0], qa[kc][1], qa[kc][2], qa[kc][3], sptr(&Qs[c * QS_STR + i]));
    }

    float oacc[8][4] = {};
    float l_lo = 0.f, l_hi = 0.f;    // per-thread partials (16 of 64 cols/row)

    for (int jt = 0; jt < 64; jt++) {
        __nv_bfloat16* Kc = (jt & 1) ? Ks1 : Ks0;
        __nv_bfloat16* Vc = (jt & 1) ? Vs1 : Vs0;
        if (jt + 1 < 64) {
            __nv_bfloat16* Kn = (jt & 1) ? Ks0 : Ks1;
            __nv_bfloat16* Vn = (jt & 1) ? Vs0 : Vs1;
            const size_t jn = (size_t)(jt + 1) * 64;
            cpa16(sptr(Kn + fr0 * KS_STR + fc0), k + (size_t)fr0 * HW + jn + fc0);
            cpa16(sptr(Kn + fr1 * KS_STR + fc1), k + (size_t)fr1 * HW + jn + fc1);
            cpa16(sptr(Vn + fr0 * KS_STR + fc0), v + (size_t)fr0 * HW + jn + fc0);
            cpa16(sptr(Vn + fr1 * KS_STR + fc1), v + (size_t)fr1 * HW + jn + fc1);
        }
        cpa_commit();
        cpa_wait<1>();
        __syncthreads();

        // ---- S = Q^T K (raw logits) ----
        float sacc[8][4] = {};
        #pragma unroll
        for (int kc = 0; kc < 4; kc++) {
            #pragma unroll
            for (int jp = 0; jp < 4; jp++) {
                const int c = kc * 16 + (quad & 1) * 8 + qr;
                const int j = jp * 16 + (quad >> 1) * 8;
                uint32_t b0, b1, b2, b3;
                ldsm4t(b0, b1, b2, b3, sptr(&Kc[c * KS_STR + j]));
                mma_bf16(sacc[2 * jp],     qa[kc], b0, b1);
                mma_bf16(sacc[2 * jp + 1], qa[kc], b2, b3);
            }
        }

        // ---- fixed-shift exp2 + pack (no reductions, no rescale) ----
        uint32_t pa[4][4];
        #pragma unroll
        for (int nt = 0; nt < 8; nt++) {
            const float p0 = ex2(fmaf(sacc[nt][0], SALPHA, -MHAT));
            const float p1 = ex2(fmaf(sacc[nt][1], SALPHA, -MHAT));
            const float p2 = ex2(fmaf(sacc[nt][2], SALPHA, -MHAT));
            const float p3 = ex2(fmaf(sacc[nt][3], SALPHA, -MHAT));
            l_lo += p0 + p1; l_hi += p2 + p3;
            pa[nt >> 1][(nt & 1) * 2]     = pk_bf16(p0, p1);
            pa[nt >> 1][(nt & 1) * 2 + 1] = pk_bf16(p2, p3);
        }

        // ---- O += P V^T ----
        #pragma unroll
        for (int kc = 0; kc < 4; kc++) {
            #pragma unroll
            for (int np = 0; np < 4; np++) {
                const int c = np * 16 + (quad >> 1) * 8 + qr;
                const int j = kc * 16 + (quad & 1) * 8;
                uint32_t b0, b1, b2, b3;
                ldsm4(b0, b1, b2, b3, sptr(&Vc[c * KS_STR + j]));
                mma_bf16(oacc[2 * np],     pa[kc], b0, b1);
                mma_bf16(oacc[2 * np + 1], pa[kc], b2, b3);
            }
        }
        __syncthreads();
    }

    // ---- final l reduction across the quad (lanes ^1, ^2) ----
    l_lo += __shfl_xor_sync(0xffffffffu, l_lo, 1);
    l_lo += __shfl_xor_sync(0xffffffffu, l_lo, 2);
    l_hi += __shfl_xor_sync(0xffffffffu, l_hi, 1);
    l_hi += __shfl_xor_sync(0xffffffffu, l_hi, 2);

    const float ilo = 1.f / l_lo, ihi = 1.f / l_hi;
    const int icol_lo = i0 + wm + gid, icol_hi = icol_lo + 8;
    #pragma unroll
    for (int nc = 0; nc < 8; nc++) {
        const int crow = b * CC + hd * DH + nc * 8 + 2 * tig;
        o[(size_t)crow * HW + icol_lo]       = __float2bfloat16(oacc[nc][0] * ilo);
        o[(size_t)(crow + 1) * HW + icol_lo] = __float2bfloat16(oacc[nc][1] * ilo);
        o[(size_t)crow * HW + icol_hi]       = __float2bfloat16(oacc[nc][2] * ihi);
        o[(size_t)(crow + 1) * HW + icol_hi] = __float2bfloat16(oacc[nc][3] * ihi);
    }
}

// ---------------------------------------------------------------------------
extern "C" void kernel_launch(void* const* d_in, const int* in_sizes, int n_in,
                              void* d_out, int out_size) {
    (void)in_sizes; (void)n_in; (void)out_size;
    const float* x      = (const float*)d_in[0];
    const float* norm_w = (const float*)d_in[1];
    const float* norm_b = (const float*)d_in[2];
    const float* qkv_w  = (const float*)d_in[3];
    const float* qkv_b  = (const float*)d_in[4];
    const float* proj_w = (const float*)d_in[5];
    const float* proj_b = (const float*)d_in[6];
    float* out = (float*)d_out;

    __nv_bfloat16 *hb, *qkvh, *ob, *qwT, *pwT;
    cudaGetSymbolAddress((void**)&hb,    g_hb);
    cudaGetSymbolAddress((void**)&qkvh,  g_qkvh);
    cudaGetSymbolAddress((void**)&ob,    g_ob);
    cudaGetSymbolAddress((void**)&qwT,   g_qkvwT);
    cudaGetSymbolAddress((void**)&pwT,   g_projwT);

    cudaFuncSetAttribute(attn_kernel, cudaFuncAttributeMaxDynamicSharedMemorySize,
                         ATTN_SMEM_BYTES);
    cudaFuncSetAttribute(gemm_bf16_kernel, cudaFuncAttributeMaxDynamicSharedMemorySize,
                         GEMM_SMEM_BYTES);

    // 0) weight convert+transpose (bf16)
    wconv_kernel<<<768, 256>>>(qkv_w, proj_w);
    // 1) GroupNorm -> bf16
    gn_kernel<<<BATCH * NGRP, 512>>>(x, norm_w, norm_b);
    // 2) qkv = qkv_w @ h + qkv_b -> bf16   (M=768, K=256, N=4096, batch=4)
    gemm_bf16_kernel<<<dim3(HW / 256, 768 / 64, BATCH), 256, GEMM_SMEM_BYTES>>>(
        qwT, hb, qkv_b, nullptr, nullptr, qkvh, 768, (long)CC * HW, (long)3 * CC * HW);
    // 3) attention (fixed-shift softmax, double-buffered K/V)
    attn_kernel<<<dim3(HW / 128, BATCH * NH), 256, ATTN_SMEM_BYTES>>>(qkvh, ob);
    // 4) out = proj_w @ o + proj_b + x  (f32)
    gemm_bf16_kernel<<<dim3(HW / 256, CC / 64, BATCH), 256, GEMM_SMEM_BYTES>>>(
        pwT, ob, proj_b, x, out, nullptr, 256, (long)CC * HW, (long)CC * HW);
}

// round 15
// speedup vs baseline: 1.0145x; 1.0145x over previous
#include <cuda_runtime.h>
#include <cuda_bf16.h>
#include <cstdint>
#include <cstddef>

// Shapes (fixed): x [4, 256, 64, 64] fp32 ; HW=4096 ; 4 heads x d=64 ; 8 groups
#define BATCH 4
#define CC    256
#define HW    4096
#define NH    4
#define DH    64
#define NGRP  8

#define OPF_SZ (BATCH * CC * HW)     // one O-partial buffer (f32)
#define LPF_SZ (BATCH * NH * HW)     // one l-partial buffer (f32)

__device__ __nv_bfloat16 g_hb[BATCH * CC * HW];         // group-normed input (bf16)
__device__ __nv_bfloat16 g_qkvh[BATCH * 3 * CC * HW];   // qkv projection (bf16)
__device__ __nv_bfloat16 g_ob[BATCH * CC * HW];         // attention output (bf16)
__device__ __nv_bfloat16 g_qkvwT[CC * 3 * CC];          // qkv_w^T bf16 [k][m]
__device__ __nv_bfloat16 g_projwT[CC * CC];             // proj_w^T bf16 [k][m]
__device__ float g_opf[4 * OPF_SZ];                     // split-KV O partials
__device__ float g_lpf[4 * LPF_SZ];                     // split-KV l partials

// ---------------------------------------------------------------------------
// helpers
// ---------------------------------------------------------------------------
__device__ __forceinline__ void mma_bf16(float* d, const uint32_t* a,
                                         uint32_t b0, uint32_t b1) {
    asm volatile(
        "mma.sync.aligned.m16n8k16.row.col.f32.bf16.bf16.f32 "
        "{%0,%1,%2,%3}, {%4,%5,%6,%7}, {%8,%9}, {%0,%1,%2,%3};\n"
        : "+f"(d[0]), "+f"(d[1]), "+f"(d[2]), "+f"(d[3])
        : "r"(a[0]), "r"(a[1]), "r"(a[2]), "r"(a[3]), "r"(b0), "r"(b1));
}

__device__ __forceinline__ void ldsm4(uint32_t& r0, uint32_t& r1, uint32_t& r2,
                                      uint32_t& r3, uint32_t addr) {
    asm volatile("ldmatrix.sync.aligned.m8n8.x4.shared.b16 {%0,%1,%2,%3}, [%4];"
                 : "=r"(r0), "=r"(r1), "=r"(r2), "=r"(r3) : "r"(addr));
}

__device__ __forceinline__ void ldsm4t(uint32_t& r0, uint32_t& r1, uint32_t& r2,
                                       uint32_t& r3, uint32_t addr) {
    asm volatile("ldmatrix.sync.aligned.m8n8.x4.trans.shared.b16 {%0,%1,%2,%3}, [%4];"
                 : "=r"(r0), "=r"(r1), "=r"(r2), "=r"(r3) : "r"(addr));
}

__device__ __forceinline__ uint32_t pk_bf16(float lo, float hi) {
    uint32_t r;
    asm("cvt.rn.bf16x2.f32 %0, %1, %2;" : "=r"(r) : "f"(hi), "f"(lo));
    return r;
}

__device__ __forceinline__ float ex2(float x) {
    float r;
    asm("ex2.approx.ftz.f32 %0, %1;" : "=f"(r) : "f"(x));
    return r;
}

__device__ __forceinline__ uint32_t sptr(const void* p) {
    return (uint32_t)__cvta_generic_to_shared(p);
}

__device__ __forceinline__ void cpa16(uint32_t saddr, const void* g) {
    asm volatile("cp.async.cg.shared.global [%0], [%1], 16;" :: "r"(saddr), "l"(g));
}
__device__ __forceinline__ void cpa_commit() {
    asm volatile("cp.async.commit_group;");
}
template <int N> __device__ __forceinline__ void cpa_wait() {
    asm volatile("cp.async.wait_group %0;" :: "n"(N));
}

// ---------------------------------------------------------------------------
// Kernel 0: weight convert+transpose: W[m][k] f32 -> W^T[k][m] bf16
// ---------------------------------------------------------------------------
__global__ void wconv_kernel(const float* __restrict__ qw, const float* __restrict__ pw) {
    const int idx = blockIdx.x * blockDim.x + threadIdx.x;   // 768*256 range
    {
        const int m = idx >> 8, k = idx & 255;
        g_qkvwT[k * 768 + m] = __float2bfloat16(qw[idx]);
    }
    if (idx < 256 * 256) {
        const int m = idx >> 8, k = idx & 255;
        g_projwT[k * 256 + m] = __float2bfloat16(pw[idx]);
    }
}

// ---------------------------------------------------------------------------
// Kernel 1: GroupNorm -> bf16. One CTA per (batch, group).
// ---------------------------------------------------------------------------
__global__ void gn_kernel(const float* __restrict__ x, const float* __restrict__ w,
                          const float* __restrict__ b) {
    const int bg = blockIdx.x;
    const int bb = bg >> 3, g = bg & 7;
    const size_t off = ((size_t)bb * CC + (size_t)g * 32) * HW;
    const float* xp = x + off;
    __nv_bfloat16* hp = g_hb + off;

    float s = 0.f, ss = 0.f;
    for (int i = threadIdx.x; i < 32 * HW; i += blockDim.x) {
        float v = xp[i]; s += v; ss += v * v;
    }
    #pragma unroll
    for (int o = 16; o; o >>= 1) {
        s  += __shfl_xor_sync(0xffffffffu, s, o);
        ss += __shfl_xor_sync(0xffffffffu, ss, o);
    }
    __shared__ float sh_s[16], sh_ss[16];
    __shared__ float sh_mean, sh_rstd;
    const int wid = threadIdx.x >> 5, lid = threadIdx.x & 31;
    if (lid == 0) { sh_s[wid] = s; sh_ss[wid] = ss; }
    __syncthreads();
    if (threadIdx.x == 0) {
        float t = 0.f, tt = 0.f;
        const int nw = blockDim.x >> 5;
        for (int i = 0; i < nw; i++) { t += sh_s[i]; tt += sh_ss[i]; }
        const float inv = 1.f / (32.f * HW);
        float mean = t * inv;
        float var = tt * inv - mean * mean;
        sh_mean = mean;
        sh_rstd = rsqrtf(var + 1e-5f);
    }
    __syncthreads();
    const float mean = sh_mean, rstd = sh_rstd;
    for (int idx = threadIdx.x; idx < 16 * HW; idx += blockDim.x) {
        const int i = idx * 2;
        const int c = g * 32 + (i >> 12);
        const float sc = rstd * w[c];
        float2 t = *(const float2*)(xp + i);
        *(uint32_t*)(hp + i) = pk_bf16((t.x - mean) * sc + b[c],
                                       (t.y - mean) * sc + b[c]);
    }
}

// ---------------------------------------------------------------------------
// Kernel 2/4: bf16 tensor-core GEMM, 64x64 CTA tile (R12 proven config).
// ---------------------------------------------------------------------------
#define GB_STR 72

__global__ void __launch_bounds__(256) gemm_bf16_kernel(
        const __nv_bfloat16* __restrict__ WT, const __nv_bfloat16* __restrict__ X,
        const float* __restrict__ bias, const float* __restrict__ resid,
        float* __restrict__ Y, __nv_bfloat16* __restrict__ Ybf,
        int Mdim, long xBatch, long yBatch) {
    __shared__ __nv_bfloat16 As[2][64 * GB_STR];
    __shared__ __nv_bfloat16 Bs[2][64 * GB_STR];

    const int n0 = blockIdx.x * 64, m0 = blockIdx.y * 64, bb = blockIdx.z;
    const __nv_bfloat16* Xb = X + (size_t)bb * xBatch;

    const int tid = threadIdx.x;
    const int warp = tid >> 5, lane = tid & 31;
    const int gid = lane >> 2, tig = lane & 3;
    const int quad = lane >> 3, qr = lane & 7;
    const int wm = (warp >> 1) * 16, wn = (warp & 1) * 32;

    auto issue = [&](int k0, int s) {
        #pragma unroll
        for (int t = 0; t < 2; t++) {
            const int idx = tid + t * 256;
            const int row = idx >> 3, blk = (idx & 7) * 8;
            cpa16(sptr(&As[s][row * GB_STR + blk]), WT + (size_t)(k0 + row) * Mdim + m0 + blk);
            cpa16(sptr(&Bs[s][row * GB_STR + blk]), Xb + (size_t)(k0 + row) * HW + n0 + blk);
        }
    };

    float acc[4][4] = {};

    issue(0, 0);
    cpa_commit();

    #pragma unroll
    for (int kt = 0; kt < 4; kt++) {
        const int cur = kt & 1;
        if (kt < 3) issue((kt + 1) * 64, cur ^ 1);
        cpa_commit();
        cpa_wait<1>();
        __syncthreads();

        #pragma unroll
        for (int kc = 0; kc < 4; kc++) {
            uint32_t qa[4];
            ldsm4t(qa[0], qa[1], qa[2], qa[3],
                   sptr(&As[cur][(kc * 16 + (quad >> 1) * 8 + qr) * GB_STR
                                 + wm + (quad & 1) * 8]));
            #pragma unroll
            for (int jp = 0; jp < 2; jp++) {
                uint32_t b0, b1, b2, b3;
                ldsm4t(b0, b1, b2, b3,
                       sptr(&Bs[cur][(kc * 16 + (quad & 1) * 8 + qr) * GB_STR
                                     + wn + jp * 16 + (quad >> 1) * 8]));
                mma_bf16(acc[2 * jp],     qa, b0, b1);
                mma_bf16(acc[2 * jp + 1], qa, b2, b3);
            }
        }
        __syncthreads();
    }

    const int mr0 = m0 + wm + gid;
    const float b0 = bias[mr0], b1 = bias[mr0 + 8];
    #pragma unroll
    for (int nt = 0; nt < 4; nt++) {
        const int col = n0 + wn + nt * 8 + 2 * tig;
        const size_t i0 = (size_t)bb * yBatch + (size_t)mr0 * HW + col;
        const size_t i1 = (size_t)bb * yBatch + (size_t)(mr0 + 8) * HW + col;
        if (Ybf) {
            *(uint32_t*)(Ybf + i0) = pk_bf16(acc[nt][0] + b0, acc[nt][1] + b0);
            *(uint32_t*)(Ybf + i1) = pk_bf16(acc[nt][2] + b1, acc[nt][3] + b1);
        } else {
            float2 r0 = make_float2(acc[nt][0] + b0, acc[nt][1] + b0);
            float2 r1 = make_float2(acc[nt][2] + b1, acc[nt][3] + b1);
            float2 x0 = *(const float2*)(resid + i0);
            float2 x1 = *(const float2*)(resid + i1);
            r0.x += x0.x; r0.y += x0.y; r1.x += x1.x; r1.y += x1.y;
            *(float2*)(Y + i0) = r0;
            *(float2*)(Y + i1) = r1;
        }
    }
}

// ---------------------------------------------------------------------------
// Kernel 3: flash attention, 4-way split-KV. blockIdx.z = quarter (16 j-tiles).
// Writes raw O partial (f32, no /l) and l partial. Fixed-shift softmax means
// partials combine by simple addition. Double-buffered K/V cp.async.
// ---------------------------------------------------------------------------
#define QS_STR 136
#define KS_STR 72
#define ATTN_SMEM_BYTES ((8704 + 2 * 4608 + 2 * 4608) * 2)   // 54272
#define SALPHA 0.18033688011112042f   // 0.125 * log2(e)
#define MHAT   10.0f                  // fixed exp2-domain shift

__global__ void __launch_bounds__(256, 2) attn_kernel(
        const __nv_bfloat16* __restrict__ qkv,
        float* __restrict__ opart, float* __restrict__ lpart) {
    extern __shared__ __nv_bfloat16 smb[];
    __nv_bfloat16* Qs = smb;                    // [64][136]
    __nv_bfloat16* Ks0 = smb + 8704;            // [64][72]
    __nv_bfloat16* Ks1 = Ks0 + 4608;
    __nv_bfloat16* Vs0 = Ks1 + 4608;
    __nv_bfloat16* Vs1 = Vs0 + 4608;

    const int bh = blockIdx.y, b = bh >> 2, hd = bh & 3;
    const int i0 = blockIdx.x * 128;
    const int jq = blockIdx.z;
    const size_t jb = (size_t)jq * 1024;        // j element offset of this quarter
    const size_t base = (size_t)b * 3 * CC * HW;
    const __nv_bfloat16* q = qkv + base + (size_t)(hd * DH) * HW;
    const __nv_bfloat16* k = qkv + base + (size_t)(CC + hd * DH) * HW;
    const __nv_bfloat16* v = qkv + base + (size_t)(2 * CC + hd * DH) * HW;

    const int tid  = threadIdx.x;
    const int warp = tid >> 5, lane = tid & 31;
    const int gid = lane >> 2, tig = lane & 3;
    const int wm = warp * 16;
    const int quad = lane >> 3, qr = lane & 7;

    const int fr0 = tid >> 3,          fc0 = (tid & 7) * 8;
    const int fr1 = (tid + 256) >> 3,  fc1 = fc0;

    #pragma unroll
    for (int t = 0; t < 4; t++) {
        const int idx = tid + t * 256;
        const int c = idx >> 4, i8 = (idx & 15) * 8;
        cpa16(sptr(Qs + c * QS_STR + i8), q + (size_t)c * HW + i0 + i8);
    }
    cpa_commit();
    cpa16(sptr(Ks0 + fr0 * KS_STR + fc0), k + (size_t)fr0 * HW + jb + fc0);
    cpa16(sptr(Ks0 + fr1 * KS_STR + fc1), k + (size_t)fr1 * HW + jb + fc1);
    cpa16(sptr(Vs0 + fr0 * KS_STR + fc0), v + (size_t)fr0 * HW + jb + fc0);
    cpa16(sptr(Vs0 + fr1 * KS_STR + fc1), v + (size_t)fr1 * HW + jb + fc1);
    cpa_commit();

    cpa_wait<1>();
    __syncthreads();

    uint32_t qa[4][4];
    #pragma unroll
    for (int kc = 0; kc < 4; kc++) {
        const int c = kc * 16 + (quad >> 1) * 8 + qr;
        const int i = wm + (quad & 1) * 8;
        ldsm4t(qa[kc][0], qa[kc][1], qa[kc][2], qa[kc][3], sptr(&Qs[c * QS_STR + i]));
    }

    float oacc[8][4] = {};
    float l_lo = 0.f, l_hi = 0.f;

    for (int jt = 0; jt < 16; jt++) {
        __nv_bfloat16* Kc = (jt & 1) ? Ks1 : Ks0;
        __nv_bfloat16* Vc = (jt & 1) ? Vs1 : Vs0;
        if (jt + 1 < 16) {
            __nv_bfloat16* Kn = (jt & 1) ? Ks0 : Ks1;
            __nv_bfloat16* Vn = (jt & 1) ? Vs0 : Vs1;
            const size_t jn = jb + (size_t)(jt + 1) * 64;
            cpa16(sptr(Kn + fr0 * KS_STR + fc0), k + (size_t)fr0 * HW + jn + fc0);
            cpa16(sptr(Kn + fr1 * KS_STR + fc1), k + (size_t)fr1 * HW + jn + fc1);
            cpa16(sptr(Vn + fr0 * KS_STR + fc0), v + (size_t)fr0 * HW + jn + fc0);
            cpa16(sptr(Vn + fr1 * KS_STR + fc1), v + (size_t)fr1 * HW + jn + fc1);
        }
        cpa_commit();
        cpa_wait<1>();
        __syncthreads();

        // ---- S = Q^T K (raw logits) ----
        float sacc[8][4] = {};
        #pragma unroll
        for (int kc = 0; kc < 4; kc++) {
            #pragma unroll
            for (int jp = 0; jp < 4; jp++) {
                const int c = kc * 16 + (quad & 1) * 8 + qr;
                const int j = jp * 16 + (quad >> 1) * 8;
                uint32_t b0, b1, b2, b3;
                ldsm4t(b0, b1, b2, b3, sptr(&Kc[c * KS_STR + j]));
                mma_bf16(sacc[2 * jp],     qa[kc], b0, b1);
                mma_bf16(sacc[2 * jp + 1], qa[kc], b2, b3);
            }
        }

        // ---- fixed-shift exp2 + pack ----
        uint32_t pa[4][4];
        #pragma unroll
        for (int nt = 0; nt < 8; nt++) {
            const float p0 = ex2(fmaf(sacc[nt][0], SALPHA, -MHAT));
            const float p1 = ex2(fmaf(sacc[nt][1], SALPHA, -MHAT));
            const float p2 = ex2(fmaf(sacc[nt][2], SALPHA, -MHAT));
            const float p3 = ex2(fmaf(sacc[nt][3], SALPHA, -MHAT));
            l_lo += p0 + p1; l_hi += p2 + p3;
            pa[nt >> 1][(nt & 1) * 2]     = pk_bf16(p0, p1);
            pa[nt >> 1][(nt & 1) * 2 + 1] = pk_bf16(p2, p3);
        }

        // ---- O += P V^T ----
        #pragma unroll
        for (int kc = 0; kc < 4; kc++) {
            #pragma unroll
            for (int np = 0; np < 4; np++) {
                const int c = np * 16 + (quad >> 1) * 8 + qr;
                const int j = kc * 16 + (quad & 1) * 8;
                uint32_t b0, b1, b2, b3;
                ldsm4(b0, b1, b2, b3, sptr(&Vc[c * KS_STR + j]));
                mma_bf16(oacc[2 * np],     pa[kc], b0, b1);
                mma_bf16(oacc[2 * np + 1], pa[kc], b2, b3);
            }
        }
        __syncthreads();
    }

    // ---- l reduction across quad; write raw partials ----
    l_lo += __shfl_xor_sync(0xffffffffu, l_lo, 1);
    l_lo += __shfl_xor_sync(0xffffffffu, l_lo, 2);
    l_hi += __shfl_xor_sync(0xffffffffu, l_hi, 1);
    l_hi += __shfl_xor_sync(0xffffffffu, l_hi, 2);

    float* op = opart + (size_t)jq * OPF_SZ;
    float* lp = lpart + (size_t)jq * LPF_SZ;
    const int icol_lo = i0 + wm + gid, icol_hi = icol_lo + 8;
    if (tig == 0) {
        lp[(size_t)bh * HW + icol_lo] = l_lo;
        lp[(size_t)bh * HW + icol_hi] = l_hi;
    }
    #pragma unroll
    for (int nc = 0; nc < 8; nc++) {
        const int crow = b * CC + hd * DH + nc * 8 + 2 * tig;
        op[(size_t)crow * HW + icol_lo]       = oacc[nc][0];
        op[(size_t)(crow + 1) * HW + icol_lo] = oacc[nc][1];
        op[(size_t)crow * HW + icol_hi]       = oacc[nc][2];
        op[(size_t)(crow + 1) * HW + icol_hi] = oacc[nc][3];
    }
}

// ---------------------------------------------------------------------------
// Kernel 3b: combine split-KV partials: ob = (sum O_q) / (sum l_q), bf16.
// All partials are L2-resident (65 MB < 126 MB L2).
// ---------------------------------------------------------------------------
__global__ void comb_kernel(__nv_bfloat16* __restrict__ ob) {
    const int p = blockIdx.x * 256 + threadIdx.x;   // pair index, 2 els each
    const int i = (p & 2047) * 2;
    const int row = p >> 11;                        // b*256 + c
    const int bh = (row >> 8) * 4 + ((row & 255) >> 6);
    float ox = 0.f, oy = 0.f, li = 0.f, li1 = 0.f;
    #pragma unroll
    for (int qd = 0; qd < 4; qd++) {
        float2 t = *(const float2*)(g_opf + (size_t)qd * OPF_SZ + (size_t)row * HW + i);
        ox += t.x; oy += t.y;
        li  += g_lpf[(size_t)qd * LPF_SZ + (size_t)bh * HW + i];
        li1 += g_lpf[(size_t)qd * LPF_SZ + (size_t)bh * HW + i + 1];
    }
    *(uint32_t*)(ob + (size_t)row * HW + i) = pk_bf16(ox / li, oy / li1);
}

// ---------------------------------------------------------------------------
extern "C" void kernel_launch(void* const* d_in, const int* in_sizes, int n_in,
                              void* d_out, int out_size) {
    (void)in_sizes; (void)n_in; (void)out_size;
    const float* x      = (const float*)d_in[0];
    const float* norm_w = (const float*)d_in[1];
    const float* norm_b = (const float*)d_in[2];
    const float* qkv_w  = (const float*)d_in[3];
    const float* qkv_b  = (const float*)d_in[4];
    const float* proj_w = (const float*)d_in[5];
    const float* proj_b = (const float*)d_in[6];
    float* out = (float*)d_out;

    __nv_bfloat16 *hb, *qkvh, *ob, *qwT, *pwT;
    float *opf, *lpf;
    cudaGetSymbolAddress((void**)&hb,    g_hb);
    cudaGetSymbolAddress((void**)&qkvh,  g_qkvh);
    cudaGetSymbolAddress((void**)&ob,    g_ob);
    cudaGetSymbolAddress((void**)&qwT,   g_qkvwT);
    cudaGetSymbolAddress((void**)&pwT,   g_projwT);
    cudaGetSymbolAddress((void**)&opf,   g_opf);
    cudaGetSymbolAddress((void**)&lpf,   g_lpf);

    cudaFuncSetAttribute(attn_kernel, cudaFuncAttributeMaxDynamicSharedMemorySize,
                         ATTN_SMEM_BYTES);

    // 0) weight convert+transpose (bf16)
    wconv_kernel<<<768, 256>>>(qkv_w, proj_w);
    // 1) GroupNorm -> bf16
    gn_kernel<<<BATCH * NGRP, 512>>>(x, norm_w, norm_b);
    // 2) qkv = qkv_w @ h + qkv_b -> bf16   (M=768, K=256, N=4096, batch=4)
    gemm_bf16_kernel<<<dim3(HW / 64, 768 / 64, BATCH), 256>>>(
        qwT, hb, qkv_b, nullptr, nullptr, qkvh, 768, (long)CC * HW, (long)3 * CC * HW);
    // 3) attention, 4-way split-KV (fixed-shift softmax -> partials add)
    attn_kernel<<<dim3(HW / 128, BATCH * NH, 4), 256, ATTN_SMEM_BYTES>>>(qkvh, opf, lpf);
    // 3b) combine partials -> bf16 O
    comb_kernel<<<(BATCH * CC * HW / 2) / 256, 256>>>(ob);
    // 4) out = proj_w @ o + proj_b + x  (f32)
    gemm_bf16_kernel<<<dim3(HW / 64, CC / 64, BATCH), 256>>>(
        pwT, ob, proj_b, x, out, nullptr, 256, (long)CC * HW, (long)CC * HW);
}

// round 16
// speedup vs baseline: 1.1941x; 1.1770x over previous
#include <cuda_runtime.h>
#include <cuda_bf16.h>
#include <cuda_fp16.h>
#include <cstdint>
#include <cstddef>

// Shapes (fixed): x [4, 256, 64, 64] fp32 ; HW=4096 ; 4 heads x d=64 ; 8 groups
#define BATCH 4
#define CC    256
#define HW    4096
#define NH    4
#define DH    64
#define NGRP  8

#define OPF_SZ (BATCH * CC * HW)     // one O-partial buffer (f32)
#define LPF_SZ (BATCH * NH * HW)     // one l-partial buffer (f32)

__device__ __nv_bfloat16 g_hb[BATCH * CC * HW];         // group-normed input (bf16)
__device__ __nv_bfloat16 g_qkvh[BATCH * 3 * CC * HW];   // qkv (Q,K bf16; V fp16 bits)
__device__ __nv_bfloat16 g_ob[BATCH * CC * HW];         // attention output (bf16)
__device__ __nv_bfloat16 g_qkvwT[CC * 3 * CC];          // qkv_w^T bf16 [k][m]
__device__ __nv_bfloat16 g_projwT[CC * CC];             // proj_w^T bf16 [k][m]
__device__ float g_opf[4 * OPF_SZ];                     // split-KV O partials
__device__ float g_lpf[4 * LPF_SZ];                     // split-KV l partials
__device__ float g_gnp[BATCH * NGRP * 8 * 2];           // GN partial sums

// ---------------------------------------------------------------------------
// helpers
// ---------------------------------------------------------------------------
__device__ __forceinline__ void mma_bf16(float* d, const uint32_t* a,
                                         uint32_t b0, uint32_t b1) {
    asm volatile(
        "mma.sync.aligned.m16n8k16.row.col.f32.bf16.bf16.f32 "
        "{%0,%1,%2,%3}, {%4,%5,%6,%7}, {%8,%9}, {%0,%1,%2,%3};\n"
        : "+f"(d[0]), "+f"(d[1]), "+f"(d[2]), "+f"(d[3])
        : "r"(a[0]), "r"(a[1]), "r"(a[2]), "r"(a[3]), "r"(b0), "r"(b1));
}

__device__ __forceinline__ void mma_f16(float* d, const uint32_t* a,
                                        uint32_t b0, uint32_t b1) {
    asm volatile(
        "mma.sync.aligned.m16n8k16.row.col.f32.f16.f16.f32 "
        "{%0,%1,%2,%3}, {%4,%5,%6,%7}, {%8,%9}, {%0,%1,%2,%3};\n"
        : "+f"(d[0]), "+f"(d[1]), "+f"(d[2]), "+f"(d[3])
        : "r"(a[0]), "r"(a[1]), "r"(a[2]), "r"(a[3]), "r"(b0), "r"(b1));
}

__device__ __forceinline__ void ldsm4(uint32_t& r0, uint32_t& r1, uint32_t& r2,
                                      uint32_t& r3, uint32_t addr) {
    asm volatile("ldmatrix.sync.aligned.m8n8.x4.shared.b16 {%0,%1,%2,%3}, [%4];"
                 : "=r"(r0), "=r"(r1), "=r"(r2), "=r"(r3) : "r"(addr));
}

__device__ __forceinline__ void ldsm4t(uint32_t& r0, uint32_t& r1, uint32_t& r2,
                                       uint32_t& r3, uint32_t addr) {
    asm volatile("ldmatrix.sync.aligned.m8n8.x4.trans.shared.b16 {%0,%1,%2,%3}, [%4];"
                 : "=r"(r0), "=r"(r1), "=r"(r2), "=r"(r3) : "r"(addr));
}

__device__ __forceinline__ uint32_t pk_bf16(float lo, float hi) {
    uint32_t r;
    asm("cvt.rn.bf16x2.f32 %0, %1, %2;" : "=r"(r) : "f"(hi), "f"(lo));
    return r;
}

__device__ __forceinline__ uint32_t pk_f16(float lo, float hi) {
    uint32_t r;
    asm("cvt.rn.f16x2.f32 %0, %1, %2;" : "=r"(r) : "f"(hi), "f"(lo));
    return r;
}

__device__ __forceinline__ uint32_t h2ex2(uint32_t x) {
    uint32_t r;
    asm("ex2.approx.f16x2 %0, %1;" : "=r"(r) : "r"(x));
    return r;
}

__device__ __forceinline__ uint32_t hadd2(uint32_t a, uint32_t b) {
    uint32_t r;
    asm("add.rn.f16x2 %0, %1, %2;" : "=r"(r) : "r"(a), "r"(b));
    return r;
}

__device__ __forceinline__ uint32_t sptr(const void* p) {
    return (uint32_t)__cvta_generic_to_shared(p);
}

__device__ __forceinline__ void cpa16(uint32_t saddr, const void* g) {
    asm volatile("cp.async.cg.shared.global [%0], [%1], 16;" :: "r"(saddr), "l"(g));
}
__device__ __forceinline__ void cpa_commit() {
    asm volatile("cp.async.commit_group;");
}
template <int N> __device__ __forceinline__ void cpa_wait() {
    asm volatile("cp.async.wait_group %0;" :: "n"(N));
}

// ---------------------------------------------------------------------------
// Kernel 0: weight convert+transpose: W[m][k] f32 -> W^T[k][m] bf16
// ---------------------------------------------------------------------------
__global__ void wconv_kernel(const float* __restrict__ qw, const float* __restrict__ pw) {
    const int idx = blockIdx.x * blockDim.x + threadIdx.x;   // 768*256 range
    {
        const int m = idx >> 8, k = idx & 255;
        g_qkvwT[k * 768 + m] = __float2bfloat16(qw[idx]);
    }
    if (idx < 256 * 256) {
        const int m = idx >> 8, k = idx & 255;
        g_projwT[k * 256 + m] = __float2bfloat16(pw[idx]);
    }
}

// ---------------------------------------------------------------------------
// Kernel 1a: GroupNorm partial sums. 256 CTAs: (bg, slice of 4 channels).
// ---------------------------------------------------------------------------
__global__ void gn_part(const float* __restrict__ x) {
    const int bg = blockIdx.x >> 3, sl = blockIdx.x & 7;
    const int bb = bg >> 3, g = bg & 7;
    const float* xp = x + ((size_t)bb * CC + (size_t)g * 32 + sl * 4) * HW;
    float s = 0.f, ss = 0.f;
    for (int i = threadIdx.x; i < 4 * HW; i += 256) {
        float v = xp[i]; s += v; ss += v * v;
    }
    #pragma unroll
    for (int o = 16; o; o >>= 1) {
        s  += __shfl_xor_sync(0xffffffffu, s, o);
        ss += __shfl_xor_sync(0xffffffffu, ss, o);
    }
    __shared__ float sh[8][2];
    const int wid = threadIdx.x >> 5;
    if ((threadIdx.x & 31) == 0) { sh[wid][0] = s; sh[wid][1] = ss; }
    __syncthreads();
    if (threadIdx.x == 0) {
        float t = 0.f, tt = 0.f;
        for (int i = 0; i < 8; i++) { t += sh[i][0]; tt += sh[i][1]; }
        g_gnp[blockIdx.x * 2]     = t;
        g_gnp[blockIdx.x * 2 + 1] = tt;
    }
}

// ---------------------------------------------------------------------------
// Kernel 1b: GroupNorm apply -> bf16. 512 CTAs: 2 channels each.
// ---------------------------------------------------------------------------
__global__ void gn_apply(const float* __restrict__ x, const float* __restrict__ w,
                         const float* __restrict__ b) {
    const int row = blockIdx.x * 2;            // global channel index (0..1023)
    const int bb = row >> 8, cin = row & 255;
    const int bg = bb * 8 + (cin >> 5);
    float t = 0.f, tt = 0.f;
    #pragma unroll
    for (int i = 0; i < 8; i++) {
        t  += g_gnp[(bg * 8 + i) * 2];
        tt += g_gnp[(bg * 8 + i) * 2 + 1];
    }
    const float inv = 1.f / (32.f * HW);
    const float mean = t * inv;
    const float rstd = rsqrtf(tt * inv - mean * mean + 1e-5f);

    const float* xp = x + (size_t)row * HW;
    __nv_bfloat16* hp = g_hb + (size_t)row * HW;
    #pragma unroll
    for (int ch = 0; ch < 2; ch++) {
        const int c = cin + ch;
        const float sc = rstd * w[c], bo = b[c] - mean * sc;
        const float* xr = xp + ch * HW;
        __nv_bfloat16* hr = hp + ch * HW;
        for (int idx = threadIdx.x; idx < HW / 2; idx += 256) {
            float2 v = *(const float2*)(xr + idx * 2);
            *(uint32_t*)(hr + idx * 2) = pk_bf16(v.x * sc + bo, v.y * sc + bo);
        }
    }
}

// ---------------------------------------------------------------------------
// Kernel 2/4: bf16 tensor-core GEMM, 64x64 CTA tile (R12 proven config).
// qkv mode (Ybf): rows 0..511 (Q,K) bf16; rows 512..767 (V) fp16.
// ---------------------------------------------------------------------------
#define GB_STR 72

__global__ void __launch_bounds__(256) gemm_bf16_kernel(
        const __nv_bfloat16* __restrict__ WT, const __nv_bfloat16* __restrict__ X,
        const float* __restrict__ bias, const float* __restrict__ resid,
        float* __restrict__ Y, __nv_bfloat16* __restrict__ Ybf,
        int Mdim, long xBatch, long yBatch) {
    __shared__ __nv_bfloat16 As[2][64 * GB_STR];
    __shared__ __nv_bfloat16 Bs[2][64 * GB_STR];

    const int n0 = blockIdx.x * 64, m0 = blockIdx.y * 64, bb = blockIdx.z;
    const __nv_bfloat16* Xb = X + (size_t)bb * xBatch;

    const int tid = threadIdx.x;
    const int warp = tid >> 5, lane = tid & 31;
    const int gid = lane >> 2, tig = lane & 3;
    const int quad = lane >> 3, qr = lane & 7;
    const int wm = (warp >> 1) * 16, wn = (warp & 1) * 32;

    auto issue = [&](int k0, int s) {
        #pragma unroll
        for (int t = 0; t < 2; t++) {
            const int idx = tid + t * 256;
            const int row = idx >> 3, blk = (idx & 7) * 8;
            cpa16(sptr(&As[s][row * GB_STR + blk]), WT + (size_t)(k0 + row) * Mdim + m0 + blk);
            cpa16(sptr(&Bs[s][row * GB_STR + blk]), Xb + (size_t)(k0 + row) * HW + n0 + blk);
        }
    };

    float acc[4][4] = {};

    issue(0, 0);
    cpa_commit();

    #pragma unroll
    for (int kt = 0; kt < 4; kt++) {
        const int cur = kt & 1;
        if (kt < 3) issue((kt + 1) * 64, cur ^ 1);
        cpa_commit();
        cpa_wait<1>();
        __syncthreads();

        #pragma unroll
        for (int kc = 0; kc < 4; kc++) {
            uint32_t qa[4];
            ldsm4t(qa[0], qa[1], qa[2], qa[3],
                   sptr(&As[cur][(kc * 16 + (quad >> 1) * 8 + qr) * GB_STR
                                 + wm + (quad & 1) * 8]));
            #pragma unroll
            for (int jp = 0; jp < 2; jp++) {
                uint32_t b0, b1, b2, b3;
                ldsm4t(b0, b1, b2, b3,
                       sptr(&Bs[cur][(kc * 16 + (quad & 1) * 8 + qr) * GB_STR
                                     + wn + jp * 16 + (quad >> 1) * 8]));
                mma_bf16(acc[2 * jp],     qa, b0, b1);
                mma_bf16(acc[2 * jp + 1], qa, b2, b3);
            }
        }
        __syncthreads();
    }

    const int mr0 = m0 + wm + gid;
    const float b0 = bias[mr0], b1 = bias[mr0 + 8];
    #pragma unroll
    for (int nt = 0; nt < 4; nt++) {
        const int col = n0 + wn + nt * 8 + 2 * tig;
        const size_t i0 = (size_t)bb * yBatch + (size_t)mr0 * HW + col;
        const size_t i1 = (size_t)bb * yBatch + (size_t)(mr0 + 8) * HW + col;
        if (Ybf) {
            if (m0 < 512) {   // Q,K: bf16
                *(uint32_t*)(Ybf + i0) = pk_bf16(acc[nt][0] + b0, acc[nt][1] + b0);
                *(uint32_t*)(Ybf + i1) = pk_bf16(acc[nt][2] + b1, acc[nt][3] + b1);
            } else {          // V: fp16 bits
                *(uint32_t*)(Ybf + i0) = pk_f16(acc[nt][0] + b0, acc[nt][1] + b0);
                *(uint32_t*)(Ybf + i1) = pk_f16(acc[nt][2] + b1, acc[nt][3] + b1);
            }
        } else {
            float2 r0 = make_float2(acc[nt][0] + b0, acc[nt][1] + b0);
            float2 r1 = make_float2(acc[nt][2] + b1, acc[nt][3] + b1);
            float2 x0 = *(const float2*)(resid + i0);
            float2 x1 = *(const float2*)(resid + i1);
            r0.x += x0.x; r0.y += x0.y; r1.x += x1.x; r1.y += x1.y;
            *(float2*)(Y + i0) = r0;
            *(float2*)(Y + i1) = r1;
        }
    }
}

// ---------------------------------------------------------------------------
// Kernel 3: flash attention, 4-way split-KV, fp16x2 softmax.
// p = 2^(s*SALPHA - MHAT) computed pairwise via ex2.approx.f16x2; P,V fp16;
// PV mma f16. l accumulated per-tile in half2, folded to f32.
// ---------------------------------------------------------------------------
#define QS_STR 136
#define KS_STR 72
#define ATTN_SMEM_BYTES ((8704 + 2 * 4608 + 2 * 4608) * 2)   // 54272
#define SALPHA 0.18033688011112042f   // 0.125 * log2(e)
#define MHAT   10.0f                  // fixed exp2-domain shift

__global__ void __launch_bounds__(256, 2) attn_kernel(
        const __nv_bfloat16* __restrict__ qkv,
        float* __restrict__ opart, float* __restrict__ lpart) {
    extern __shared__ __nv_bfloat16 smb[];
    __nv_bfloat16* Qs = smb;                    // [64][136]
    __nv_bfloat16* Ks0 = smb + 8704;            // [64][72]
    __nv_bfloat16* Ks1 = Ks0 + 4608;
    __nv_bfloat16* Vs0 = Ks1 + 4608;
    __nv_bfloat16* Vs1 = Vs0 + 4608;

    const int bh = blockIdx.y, b = bh >> 2, hd = bh & 3;
    const int i0 = blockIdx.x * 128;
    const int jq = blockIdx.z;
    const size_t jb = (size_t)jq * 1024;
    const size_t base = (size_t)b * 3 * CC * HW;
    const __nv_bfloat16* q = qkv + base + (size_t)(hd * DH) * HW;
    const __nv_bfloat16* k = qkv + base + (size_t)(CC + hd * DH) * HW;
    const __nv_bfloat16* v = qkv + base + (size_t)(2 * CC + hd * DH) * HW;

    const int tid  = threadIdx.x;
    const int warp = tid >> 5, lane = tid & 31;
    const int gid = lane >> 2, tig = lane & 3;
    const int wm = warp * 16;
    const int quad = lane >> 3, qr = lane & 7;

    const int fr0 = tid >> 3,          fc0 = (tid & 7) * 8;
    const int fr1 = (tid + 256) >> 3,  fc1 = fc0;

    #pragma unroll
    for (int t = 0; t < 4; t++) {
        const int idx = tid + t * 256;
        const int c = idx >> 4, i8 = (idx & 15) * 8;
        cpa16(sptr(Qs + c * QS_STR + i8), q + (size_t)c * HW + i0 + i8);
    }
    cpa_commit();
    cpa16(sptr(Ks0 + fr0 * KS_STR + fc0), k + (size_t)fr0 * HW + jb + fc0);
    cpa16(sptr(Ks0 + fr1 * KS_STR + fc1), k + (size_t)fr1 * HW + jb + fc1);
    cpa16(sptr(Vs0 + fr0 * KS_STR + fc0), v + (size_t)fr0 * HW + jb + fc0);
    cpa16(sptr(Vs0 + fr1 * KS_STR + fc1), v + (size_t)fr1 * HW + jb + fc1);
    cpa_commit();

    cpa_wait<1>();
    __syncthreads();

    uint32_t qa[4][4];
    #pragma unroll
    for (int kc = 0; kc < 4; kc++) {
        const int c = kc * 16 + (quad >> 1) * 8 + qr;
        const int i = wm + (quad & 1) * 8;
        ldsm4t(qa[kc][0], qa[kc][1], qa[kc][2], qa[kc][3], sptr(&Qs[c * QS_STR + i]));
    }

    float oacc[8][4] = {};
    float l_lo = 0.f, l_hi = 0.f;

    for (int jt = 0; jt < 16; jt++) {
        __nv_bfloat16* Kc = (jt & 1) ? Ks1 : Ks0;
        __nv_bfloat16* Vc = (jt & 1) ? Vs1 : Vs0;
        if (jt + 1 < 16) {
            __nv_bfloat16* Kn = (jt & 1) ? Ks0 : Ks1;
            __nv_bfloat16* Vn = (jt & 1) ? Vs0 : Vs1;
            const size_t jn = jb + (size_t)(jt + 1) * 64;
            cpa16(sptr(Kn + fr0 * KS_STR + fc0), k + (size_t)fr0 * HW + jn + fc0);
            cpa16(sptr(Kn + fr1 * KS_STR + fc1), k + (size_t)fr1 * HW + jn + fc1);
            cpa16(sptr(Vn + fr0 * KS_STR + fc0), v + (size_t)fr0 * HW + jn + fc0);
            cpa16(sptr(Vn + fr1 * KS_STR + fc1), v + (size_t)fr1 * HW + jn + fc1);
        }
        cpa_commit();
        cpa_wait<1>();
        __syncthreads();

        // ---- S = Q^T K (raw logits, bf16 mma) ----
        float sacc[8][4] = {};
        #pragma unroll
        for (int kc = 0; kc < 4; kc++) {
            #pragma unroll
            for (int jp = 0; jp < 4; jp++) {
                const int c = kc * 16 + (quad & 1) * 8 + qr;
                const int j = jp * 16 + (quad >> 1) * 8;
                uint32_t b0, b1, b2, b3;
                ldsm4t(b0, b1, b2, b3, sptr(&Kc[c * KS_STR + j]));
                mma_bf16(sacc[2 * jp],     qa[kc], b0, b1);
                mma_bf16(sacc[2 * jp + 1], qa[kc], b2, b3);
            }
        }

        // ---- fixed-shift exp2 via f16x2 MUFU pairs; l in half2 per tile ----
        uint32_t pa[4][4];
        uint32_t hs_lo = 0u, hs_hi = 0u;
        #pragma unroll
        for (int nt = 0; nt < 8; nt++) {
            const float f0 = fmaf(sacc[nt][0], SALPHA, -MHAT);
            const float f1 = fmaf(sacc[nt][1], SALPHA, -MHAT);
            const float f2 = fmaf(sacc[nt][2], SALPHA, -MHAT);
            const float f3 = fmaf(sacc[nt][3], SALPHA, -MHAT);
            const uint32_t plo = h2ex2(pk_f16(f0, f1));
            const uint32_t phi = h2ex2(pk_f16(f2, f3));
            hs_lo = hadd2(hs_lo, plo);
            hs_hi = hadd2(hs_hi, phi);
            pa[nt >> 1][(nt & 1) * 2]     = plo;
            pa[nt >> 1][(nt & 1) * 2 + 1] = phi;
        }
        {
            __half2 a = *reinterpret_cast<__half2*>(&hs_lo);
            __half2 c = *reinterpret_cast<__half2*>(&hs_hi);
            float2 fa = __half22float2(a), fc = __half22float2(c);
            l_lo += fa.x + fa.y;
            l_hi += fc.x + fc.y;
        }

        // ---- O += P V^T (f16 mma; V stored as fp16 bits) ----
        #pragma unroll
        for (int kc = 0; kc < 4; kc++) {
            #pragma unroll
            for (int np = 0; np < 4; np++) {
                const int c = np * 16 + (quad >> 1) * 8 + qr;
                const int j = kc * 16 + (quad & 1) * 8;
                uint32_t b0, b1, b2, b3;
                ldsm4(b0, b1, b2, b3, sptr(&Vc[c * KS_STR + j]));
                mma_f16(oacc[2 * np],     pa[kc], b0, b1);
                mma_f16(oacc[2 * np + 1], pa[kc], b2, b3);
            }
        }
        __syncthreads();
    }

    // ---- l reduction across quad; write raw partials ----
    l_lo += __shfl_xor_sync(0xffffffffu, l_lo, 1);
    l_lo += __shfl_xor_sync(0xffffffffu, l_lo, 2);
    l_hi += __shfl_xor_sync(0xffffffffu, l_hi, 1);
    l_hi += __shfl_xor_sync(0xffffffffu, l_hi, 2);

    float* op = opart + (size_t)jq * OPF_SZ;
    float* lp = lpart + (size_t)jq * LPF_SZ;
    const int icol_lo = i0 + wm + gid, icol_hi = icol_lo + 8;
    if (tig == 0) {
        lp[(size_t)bh * HW + icol_lo] = l_lo;
        lp[(size_t)bh * HW + icol_hi] = l_hi;
    }
    #pragma unroll
    for (int nc = 0; nc < 8; nc++) {
        const int crow = b * CC + hd * DH + nc * 8 + 2 * tig;
        op[(size_t)crow * HW + icol_lo]       = oacc[nc][0];
        op[(size_t)(crow + 1) * HW + icol_lo] = oacc[nc][1];
        op[(size_t)crow * HW + icol_hi]       = oacc[nc][2];
        op[(size_t)(crow + 1) * HW + icol_hi] = oacc[nc][3];
    }
}

// ---------------------------------------------------------------------------
// Kernel 3b: combine split-KV partials (float4): ob = (sum O_q)/(sum l_q).
// ---------------------------------------------------------------------------
__global__ void comb_kernel(__nv_bfloat16* __restrict__ ob) {
    const int p = blockIdx.x * 256 + threadIdx.x;   // 4 els each
    const int i = (p & 1023) * 4;
    const int row = p >> 10;                        // b*256 + c
    const int bh = (row >> 8) * 4 + ((row & 255) >> 6);
    float4 o = make_float4(0.f, 0.f, 0.f, 0.f);
    float4 lv = make_float4(0.f, 0.f, 0.f, 0.f);
    #pragma unroll
    for (int qd = 0; qd < 4; qd++) {
        float4 t = *(const float4*)(g_opf + (size_t)qd * OPF_SZ + (size_t)row * HW + i);
        o.x += t.x; o.y += t.y; o.z += t.z; o.w += t.w;
        float4 lt = *(const float4*)(g_lpf + (size_t)qd * LPF_SZ + (size_t)bh * HW + i);
        lv.x += lt.x; lv.y += lt.y; lv.z += lt.z; lv.w += lt.w;
    }
    uint2 r;
    r.x = pk_bf16(o.x / lv.x, o.y / lv.y);
    r.y = pk_bf16(o.z / lv.z, o.w / lv.w);
    *(uint2*)(ob + (size_t)row * HW + i) = r;
}

// ---------------------------------------------------------------------------
extern "C" void kernel_launch(void* const* d_in, const int* in_sizes, int n_in,
                              void* d_out, int out_size) {
    (void)in_sizes; (void)n_in; (void)out_size;
    const float* x      = (const float*)d_in[0];
    const float* norm_w = (const float*)d_in[1];
    const float* norm_b = (const float*)d_in[2];
    const float* qkv_w  = (const float*)d_in[3];
    const float* qkv_b  = (const float*)d_in[4];
    const float* proj_w = (const float*)d_in[5];
    const float* proj_b = (const float*)d_in[6];
    float* out = (float*)d_out;

    __nv_bfloat16 *hb, *qkvh, *ob, *qwT, *pwT;
    float *opf, *lpf;
    cudaGetSymbolAddress((void**)&hb,    g_hb);
    cudaGetSymbolAddress((void**)&qkvh,  g_qkvh);
    cudaGetSymbolAddress((void**)&ob,    g_ob);
    cudaGetSymbolAddress((void**)&qwT,   g_qkvwT);
    cudaGetSymbolAddress((void**)&pwT,   g_projwT);
    cudaGetSymbolAddress((void**)&opf,   g_opf);
    cudaGetSymbolAddress((void**)&lpf,   g_lpf);

    cudaFuncSetAttribute(attn_kernel, cudaFuncAttributeMaxDynamicSharedMemorySize,
                         ATTN_SMEM_BYTES);

    // 0) weight convert+transpose (bf16)
    wconv_kernel<<<768, 256>>>(qkv_w, proj_w);
    // 1) GroupNorm: partial sums, then apply -> bf16
    gn_part<<<256, 256>>>(x);
    gn_apply<<<512, 256>>>(x, norm_w, norm_b);
    // 2) qkv = qkv_w @ h + qkv_b -> Q,K bf16 / V fp16
    gemm_bf16_kernel<<<dim3(HW / 64, 768 / 64, BATCH), 256>>>(
        qwT, hb, qkv_b, nullptr, nullptr, qkvh, 768, (long)CC * HW, (long)3 * CC * HW);
    // 3) attention, 4-way split-KV (fp16x2 softmax)
    attn_kernel<<<dim3(HW / 128, BATCH * NH, 4), 256, ATTN_SMEM_BYTES>>>(qkvh, opf, lpf);
    // 3b) combine partials -> bf16 O
    comb_kernel<<<(BATCH * CC * HW / 4) / 256, 256>>>(ob);
    // 4) out = proj_w @ o + proj_b + x  (f32)
    gemm_bf16_kernel<<<dim3(HW / 64, CC / 64, BATCH), 256>>>(
        pwT, ob, proj_b, x, out, nullptr, 256, (long)CC * HW, (long)CC * HW);
}

// round 17
// speedup vs baseline: 1.2029x; 1.0074x over previous
#include <cuda_runtime.h>
#include <cuda_bf16.h>
#include <cuda_fp16.h>
#include <cstdint>
#include <cstddef>

// Shapes (fixed): x [4, 256, 64, 64] fp32 ; HW=4096 ; 4 heads x d=64 ; 8 groups
#define BATCH 4
#define CC    256
#define HW    4096
#define NH    4
#define DH    64
#define NGRP  8

#define OPF_SZ (BATCH * CC * HW)     // one O-partial buffer (f32)
#define LPF_SZ (BATCH * NH * HW)     // one l-partial buffer (f32)

__device__ __nv_bfloat16 g_hb[BATCH * CC * HW];         // group-normed input (bf16)
__device__ __nv_bfloat16 g_qkvh[BATCH * 3 * CC * HW];   // qkv (Q,K bf16; V fp16 bits)
__device__ __nv_bfloat16 g_ob[BATCH * CC * HW];         // attention output (bf16)
__device__ __nv_bfloat16 g_qkvwT[CC * 3 * CC];          // qkv_w^T bf16 [k][m]
__device__ __nv_bfloat16 g_projwT[CC * CC];             // proj_w^T bf16 [k][m]
__device__ float g_opf[4 * OPF_SZ];                     // split-KV O partials
__device__ float g_lpf[4 * LPF_SZ];                     // split-KV l partials
__device__ float g_gnp[BATCH * NGRP * 8 * 2];           // GN partial sums

// ---------------------------------------------------------------------------
// helpers
// ---------------------------------------------------------------------------
__device__ __forceinline__ void mma_bf16(float* d, const uint32_t* a,
                                         uint32_t b0, uint32_t b1) {
    asm volatile(
        "mma.sync.aligned.m16n8k16.row.col.f32.bf16.bf16.f32 "
        "{%0,%1,%2,%3}, {%4,%5,%6,%7}, {%8,%9}, {%0,%1,%2,%3};\n"
        : "+f"(d[0]), "+f"(d[1]), "+f"(d[2]), "+f"(d[3])
        : "r"(a[0]), "r"(a[1]), "r"(a[2]), "r"(a[3]), "r"(b0), "r"(b1));
}

__device__ __forceinline__ void mma_f16(float* d, const uint32_t* a,
                                        uint32_t b0, uint32_t b1) {
    asm volatile(
        "mma.sync.aligned.m16n8k16.row.col.f32.f16.f16.f32 "
        "{%0,%1,%2,%3}, {%4,%5,%6,%7}, {%8,%9}, {%0,%1,%2,%3};\n"
        : "+f"(d[0]), "+f"(d[1]), "+f"(d[2]), "+f"(d[3])
        : "r"(a[0]), "r"(a[1]), "r"(a[2]), "r"(a[3]), "r"(b0), "r"(b1));
}

__device__ __forceinline__ void ldsm4(uint32_t& r0, uint32_t& r1, uint32_t& r2,
                                      uint32_t& r3, uint32_t addr) {
    asm volatile("ldmatrix.sync.aligned.m8n8.x4.shared.b16 {%0,%1,%2,%3}, [%4];"
                 : "=r"(r0), "=r"(r1), "=r"(r2), "=r"(r3) : "r"(addr));
}

__device__ __forceinline__ void ldsm4t(uint32_t& r0, uint32_t& r1, uint32_t& r2,
                                       uint32_t& r3, uint32_t addr) {
    asm volatile("ldmatrix.sync.aligned.m8n8.x4.trans.shared.b16 {%0,%1,%2,%3}, [%4];"
                 : "=r"(r0), "=r"(r1), "=r"(r2), "=r"(r3) : "r"(addr));
}

__device__ __forceinline__ uint32_t pk_bf16(float lo, float hi) {
    uint32_t r;
    asm("cvt.rn.bf16x2.f32 %0, %1, %2;" : "=r"(r) : "f"(hi), "f"(lo));
    return r;
}

__device__ __forceinline__ uint32_t pk_f16(float lo, float hi) {
    uint32_t r;
    asm("cvt.rn.f16x2.f32 %0, %1, %2;" : "=r"(r) : "f"(hi), "f"(lo));
    return r;
}

__device__ __forceinline__ uint32_t h2ex2(uint32_t x) {
    uint32_t r;
    asm("ex2.approx.f16x2 %0, %1;" : "=r"(r) : "r"(x));
    return r;
}

__device__ __forceinline__ uint32_t hadd2(uint32_t a, uint32_t b) {
    uint32_t r;
    asm("add.rn.f16x2 %0, %1, %2;" : "=r"(r) : "r"(a), "r"(b));
    return r;
}

__device__ __forceinline__ uint32_t sptr(const void* p) {
    return (uint32_t)__cvta_generic_to_shared(p);
}

__device__ __forceinline__ void cpa16(uint32_t saddr, const void* g) {
    asm volatile("cp.async.cg.shared.global [%0], [%1], 16;" :: "r"(saddr), "l"(g));
}
__device__ __forceinline__ void cpa_commit() {
    asm volatile("cp.async.commit_group;");
}
template <int N> __device__ __forceinline__ void cpa_wait() {
    asm volatile("cp.async.wait_group %0;" :: "n"(N));
}

// ---------------------------------------------------------------------------
// Kernel 0: weight convert+transpose: W[m][k] f32 -> W^T[k][m] bf16
// ---------------------------------------------------------------------------
__global__ void wconv_kernel(const float* __restrict__ qw, const float* __restrict__ pw) {
    const int idx = blockIdx.x * blockDim.x + threadIdx.x;   // 768*256 range
    {
        const int m = idx >> 8, k = idx & 255;
        g_qkvwT[k * 768 + m] = __float2bfloat16(qw[idx]);
    }
    if (idx < 256 * 256) {
        const int m = idx >> 8, k = idx & 255;
        g_projwT[k * 256 + m] = __float2bfloat16(pw[idx]);
    }
}

// ---------------------------------------------------------------------------
// Kernel 1a: GroupNorm partial sums. 256 CTAs: (bg, slice of 4 channels).
// ---------------------------------------------------------------------------
__global__ void gn_part(const float* __restrict__ x) {
    const int bg = blockIdx.x >> 3, sl = blockIdx.x & 7;
    const int bb = bg >> 3, g = bg & 7;
    const float* xp = x + ((size_t)bb * CC + (size_t)g * 32 + sl * 4) * HW;
    float s = 0.f, ss = 0.f;
    for (int i = threadIdx.x; i < 4 * HW; i += 256) {
        float v = xp[i]; s += v; ss += v * v;
    }
    #pragma unroll
    for (int o = 16; o; o >>= 1) {
        s  += __shfl_xor_sync(0xffffffffu, s, o);
        ss += __shfl_xor_sync(0xffffffffu, ss, o);
    }
    __shared__ float sh[8][2];
    const int wid = threadIdx.x >> 5;
    if ((threadIdx.x & 31) == 0) { sh[wid][0] = s; sh[wid][1] = ss; }
    __syncthreads();
    if (threadIdx.x == 0) {
        float t = 0.f, tt = 0.f;
        for (int i = 0; i < 8; i++) { t += sh[i][0]; tt += sh[i][1]; }
        g_gnp[blockIdx.x * 2]     = t;
        g_gnp[blockIdx.x * 2 + 1] = tt;
    }
}

// ---------------------------------------------------------------------------
// Kernel 1b: GroupNorm apply -> bf16. 512 CTAs: 2 channels each.
// ---------------------------------------------------------------------------
__global__ void gn_apply(const float* __restrict__ x, const float* __restrict__ w,
                         const float* __restrict__ b) {
    const int row = blockIdx.x * 2;            // global channel index (0..1023)
    const int bb = row >> 8, cin = row & 255;
    const int bg = bb * 8 + (cin >> 5);
    float t = 0.f, tt = 0.f;
    #pragma unroll
    for (int i = 0; i < 8; i++) {
        t  += g_gnp[(bg * 8 + i) * 2];
        tt += g_gnp[(bg * 8 + i) * 2 + 1];
    }
    const float inv = 1.f / (32.f * HW);
    const float mean = t * inv;
    const float rstd = rsqrtf(tt * inv - mean * mean + 1e-5f);

    const float* xp = x + (size_t)row * HW;
    __nv_bfloat16* hp = g_hb + (size_t)row * HW;
    #pragma unroll
    for (int ch = 0; ch < 2; ch++) {
        const int c = cin + ch;
        const float sc = rstd * w[c], bo = b[c] - mean * sc;
        const float* xr = xp + ch * HW;
        __nv_bfloat16* hr = hp + ch * HW;
        for (int idx = threadIdx.x; idx < HW / 2; idx += 256) {
            float2 v = *(const float2*)(xr + idx * 2);
            *(uint32_t*)(hr + idx * 2) = pk_bf16(v.x * sc + bo, v.y * sc + bo);
        }
    }
}

// ---------------------------------------------------------------------------
// Kernel 2/4: bf16 tensor-core GEMM, 128m x 64n CTA tile.
// 8 warps as 4m x 2n, warp tile 32x32. LDSM:mma = 4:8 per kc.
// B-tile L2 re-reads halve vs 64m tiles. cp.async double-buffered, K=256.
// qkv mode (Ybf): rows <512 (Q,K) bf16; rows >=512 (V) fp16.
// ---------------------------------------------------------------------------
#define GA_STR 136    // As [k][m] stride (17*8: proven conflict-free class)
#define GB_STR 72     // Bs [k][n] stride
#define GEMM_SMEM_BYTES ((2 * 64 * GA_STR + 2 * 64 * GB_STR) * 2)   // 53248

__global__ void __launch_bounds__(256) gemm_bf16_kernel(
        const __nv_bfloat16* __restrict__ WT, const __nv_bfloat16* __restrict__ X,
        const float* __restrict__ bias, const float* __restrict__ resid,
        float* __restrict__ Y, __nv_bfloat16* __restrict__ Ybf,
        int Mdim, long xBatch, long yBatch) {
    extern __shared__ __nv_bfloat16 gsm[];
    __nv_bfloat16* As0 = gsm;
    __nv_bfloat16* As1 = As0 + 64 * GA_STR;
    __nv_bfloat16* Bs0 = As1 + 64 * GA_STR;
    __nv_bfloat16* Bs1 = Bs0 + 64 * GB_STR;

    const int n0 = blockIdx.x * 64, m0 = blockIdx.y * 128, bb = blockIdx.z;
    const __nv_bfloat16* Xb = X + (size_t)bb * xBatch;

    const int tid = threadIdx.x;
    const int warp = tid >> 5, lane = tid & 31;
    const int gid = lane >> 2, tig = lane & 3;
    const int quad = lane >> 3, qr = lane & 7;
    const int wm = (warp >> 1) * 32, wn = (warp & 1) * 32;

    auto issue = [&](int k0, __nv_bfloat16* A, __nv_bfloat16* B) {
        #pragma unroll
        for (int t = 0; t < 4; t++) {   // A: 64 rows x 128 m = 1024 16B chunks
            const int idx = tid + t * 256;
            const int row = idx >> 4, blk = (idx & 15) * 8;
            cpa16(sptr(A + row * GA_STR + blk), WT + (size_t)(k0 + row) * Mdim + m0 + blk);
        }
        #pragma unroll
        for (int t = 0; t < 2; t++) {   // B: 64 rows x 64 n = 512 chunks
            const int idx = tid + t * 256;
            const int row = idx >> 3, blk = (idx & 7) * 8;
            cpa16(sptr(B + row * GB_STR + blk), Xb + (size_t)(k0 + row) * HW + n0 + blk);
        }
    };

    float acc[2][4][4] = {};   // [msub][nt][4]

    issue(0, As0, Bs0);
    cpa_commit();

    #pragma unroll
    for (int kt = 0; kt < 4; kt++) {
        __nv_bfloat16* Ac = (kt & 1) ? As1 : As0;
        __nv_bfloat16* Bc = (kt & 1) ? Bs1 : Bs0;
        if (kt < 3) issue((kt + 1) * 64, (kt & 1) ? As0 : As1, (kt & 1) ? Bs0 : Bs1);
        cpa_commit();
        cpa_wait<1>();
        __syncthreads();

        #pragma unroll
        for (int kc = 0; kc < 4; kc++) {
            uint32_t qa[2][4];
            #pragma unroll
            for (int msub = 0; msub < 2; msub++)
                ldsm4t(qa[msub][0], qa[msub][1], qa[msub][2], qa[msub][3],
                       sptr(&Ac[(kc * 16 + (quad >> 1) * 8 + qr) * GA_STR
                                + wm + msub * 16 + (quad & 1) * 8]));
            #pragma unroll
            for (int jp = 0; jp < 2; jp++) {
                uint32_t b0, b1, b2, b3;
                ldsm4t(b0, b1, b2, b3,
                       sptr(&Bc[(kc * 16 + (quad & 1) * 8 + qr) * GB_STR
                                + wn + jp * 16 + (quad >> 1) * 8]));
                #pragma unroll
                for (int msub = 0; msub < 2; msub++) {
                    mma_bf16(acc[msub][2 * jp],     qa[msub], b0, b1);
                    mma_bf16(acc[msub][2 * jp + 1], qa[msub], b2, b3);
                }
            }
        }
        __syncthreads();
    }

    #pragma unroll
    for (int msub = 0; msub < 2; msub++) {
        const int mr0 = m0 + wm + msub * 16 + gid;
        const float b0 = bias[mr0], b1 = bias[mr0 + 8];
        #pragma unroll
        for (int nt = 0; nt < 4; nt++) {
            float* a = acc[msub][nt];
            const int col = n0 + wn + nt * 8 + 2 * tig;
            const size_t i0 = (size_t)bb * yBatch + (size_t)mr0 * HW + col;
            const size_t i1 = (size_t)bb * yBatch + (size_t)(mr0 + 8) * HW + col;
            if (Ybf) {
                if (m0 < 512) {   // Q,K: bf16  (tiles never straddle 512)
                    *(uint32_t*)(Ybf + i0) = pk_bf16(a[0] + b0, a[1] + b0);
                    *(uint32_t*)(Ybf + i1) = pk_bf16(a[2] + b1, a[3] + b1);
                } else {          // V: fp16 bits
                    *(uint32_t*)(Ybf + i0) = pk_f16(a[0] + b0, a[1] + b0);
                    *(uint32_t*)(Ybf + i1) = pk_f16(a[2] + b1, a[3] + b1);
                }
            } else {
                float2 r0 = make_float2(a[0] + b0, a[1] + b0);
                float2 r1 = make_float2(a[2] + b1, a[3] + b1);
                float2 x0 = *(const float2*)(resid + i0);
                float2 x1 = *(const float2*)(resid + i1);
                r0.x += x0.x; r0.y += x0.y; r1.x += x1.x; r1.y += x1.y;
                *(float2*)(Y + i0) = r0;
                *(float2*)(Y + i1) = r1;
            }
        }
    }
}

// ---------------------------------------------------------------------------
// Kernel 3: flash attention, 4-way split-KV, fp16x2 softmax (R16 proven).
// ---------------------------------------------------------------------------
#define QS_STR 136
#define KS_STR 72
#define ATTN_SMEM_BYTES ((8704 + 2 * 4608 + 2 * 4608) * 2)   // 54272
#define SALPHA 0.18033688011112042f   // 0.125 * log2(e)
#define MHAT   10.0f                  // fixed exp2-domain shift

__global__ void __launch_bounds__(256, 2) attn_kernel(
        const __nv_bfloat16* __restrict__ qkv,
        float* __restrict__ opart, float* __restrict__ lpart) {
    extern __shared__ __nv_bfloat16 smb[];
    __nv_bfloat16* Qs = smb;                    // [64][136]
    __nv_bfloat16* Ks0 = smb + 8704;            // [64][72]
    __nv_bfloat16* Ks1 = Ks0 + 4608;
    __nv_bfloat16* Vs0 = Ks1 + 4608;
    __nv_bfloat16* Vs1 = Vs0 + 4608;

    const int bh = blockIdx.y, b = bh >> 2, hd = bh & 3;
    const int i0 = blockIdx.x * 128;
    const int jq = blockIdx.z;
    const size_t jb = (size_t)jq * 1024;
    const size_t base = (size_t)b * 3 * CC * HW;
    const __nv_bfloat16* q = qkv + base + (size_t)(hd * DH) * HW;
    const __nv_bfloat16* k = qkv + base + (size_t)(CC + hd * DH) * HW;
    const __nv_bfloat16* v = qkv + base + (size_t)(2 * CC + hd * DH) * HW;

    const int tid  = threadIdx.x;
    const int warp = tid >> 5, lane = tid & 31;
    const int gid = lane >> 2, tig = lane & 3;
    const int wm = warp * 16;
    const int quad = lane >> 3, qr = lane & 7;

    const int fr0 = tid >> 3,          fc0 = (tid & 7) * 8;
    const int fr1 = (tid + 256) >> 3,  fc1 = fc0;

    #pragma unroll
    for (int t = 0; t < 4; t++) {
        const int idx = tid + t * 256;
        const int c = idx >> 4, i8 = (idx & 15) * 8;
        cpa16(sptr(Qs + c * QS_STR + i8), q + (size_t)c * HW + i0 + i8);
    }
    cpa_commit();
    cpa16(sptr(Ks0 + fr0 * KS_STR + fc0), k + (size_t)fr0 * HW + jb + fc0);
    cpa16(sptr(Ks0 + fr1 * KS_STR + fc1), k + (size_t)fr1 * HW + jb + fc1);
    cpa16(sptr(Vs0 + fr0 * KS_STR + fc0), v + (size_t)fr0 * HW + jb + fc0);
    cpa16(sptr(Vs0 + fr1 * KS_STR + fc1), v + (size_t)fr1 * HW + jb + fc1);
    cpa_commit();

    cpa_wait<1>();
    __syncthreads();

    uint32_t qa[4][4];
    #pragma unroll
    for (int kc = 0; kc < 4; kc++) {
        const int c = kc * 16 + (quad >> 1) * 8 + qr;
        const int i = wm + (quad & 1) * 8;
        ldsm4t(qa[kc][0], qa[kc][1], qa[kc][2], qa[kc][3], sptr(&Qs[c * QS_STR + i]));
    }

    float oacc[8][4] = {};
    float l_lo = 0.f, l_hi = 0.f;

    for (int jt = 0; jt < 16; jt++) {
        __nv_bfloat16* Kc = (jt & 1) ? Ks1 : Ks0;
        __nv_bfloat16* Vc = (jt & 1) ? Vs1 : Vs0;
        if (jt + 1 < 16) {
            __nv_bfloat16* Kn = (jt & 1) ? Ks0 : Ks1;
            __nv_bfloat16* Vn = (jt & 1) ? Vs0 : Vs1;
            const size_t jn = jb + (size_t)(jt + 1) * 64;
            cpa16(sptr(Kn + fr0 * KS_STR + fc0), k + (size_t)fr0 * HW + jn + fc0);
            cpa16(sptr(Kn + fr1 * KS_STR + fc1), k + (size_t)fr1 * HW + jn + fc1);
            cpa16(sptr(Vn + fr0 * KS_STR + fc0), v + (size_t)fr0 * HW + jn + fc0);
            cpa16(sptr(Vn + fr1 * KS_STR + fc1), v + (size_t)fr1 * HW + jn + fc1);
        }
        cpa_commit();
        cpa_wait<1>();
        __syncthreads();

        // ---- S = Q^T K (raw logits, bf16 mma) ----
        float sacc[8][4] = {};
        #pragma unroll
        for (int kc = 0; kc < 4; kc++) {
            #pragma unroll
            for (int jp = 0; jp < 4; jp++) {
                const int c = kc * 16 + (quad & 1) * 8 + qr;
                const int j = jp * 16 + (quad >> 1) * 8;
                uint32_t b0, b1, b2, b3;
                ldsm4t(b0, b1, b2, b3, sptr(&Kc[c * KS_STR + j]));
                mma_bf16(sacc[2 * jp],     qa[kc], b0, b1);
                mma_bf16(sacc[2 * jp + 1], qa[kc], b2, b3);
            }
        }

        // ---- fixed-shift exp2 via f16x2 MUFU pairs; l in half2 per tile ----
        uint32_t pa[4][4];
        uint32_t hs_lo = 0u, hs_hi = 0u;
        #pragma unroll
        for (int nt = 0; nt < 8; nt++) {
            const float f0 = fmaf(sacc[nt][0], SALPHA, -MHAT);
            const float f1 = fmaf(sacc[nt][1], SALPHA, -MHAT);
            const float f2 = fmaf(sacc[nt][2], SALPHA, -MHAT);
            const float f3 = fmaf(sacc[nt][3], SALPHA, -MHAT);
            const uint32_t plo = h2ex2(pk_f16(f0, f1));
            const uint32_t phi = h2ex2(pk_f16(f2, f3));
            hs_lo = hadd2(hs_lo, plo);
            hs_hi = hadd2(hs_hi, phi);
            pa[nt >> 1][(nt & 1) * 2]     = plo;
            pa[nt >> 1][(nt & 1) * 2 + 1] = phi;
        }
        {
            __half2 a = *reinterpret_cast<__half2*>(&hs_lo);
            __half2 c = *reinterpret_cast<__half2*>(&hs_hi);
            float2 fa = __half22float2(a), fc = __half22float2(c);
            l_lo += fa.x + fa.y;
            l_hi += fc.x + fc.y;
        }

        // ---- O += P V^T (f16 mma; V stored as fp16 bits) ----
        #pragma unroll
        for (int kc = 0; kc < 4; kc++) {
            #pragma unroll
            for (int np = 0; np < 4; np++) {
                const int c = np * 16 + (quad >> 1) * 8 + qr;
                const int j = kc * 16 + (quad & 1) * 8;
                uint32_t b0, b1, b2, b3;
                ldsm4(b0, b1, b2, b3, sptr(&Vc[c * KS_STR + j]));
                mma_f16(oacc[2 * np],     pa[kc], b0, b1);
                mma_f16(oacc[2 * np + 1], pa[kc], b2, b3);
            }
        }
        __syncthreads();
    }

    // ---- l reduction across quad; write raw partials ----
    l_lo += __shfl_xor_sync(0xffffffffu, l_lo, 1);
    l_lo += __shfl_xor_sync(0xffffffffu, l_lo, 2);
    l_hi += __shfl_xor_sync(0xffffffffu, l_hi, 1);
    l_hi += __shfl_xor_sync(0xffffffffu, l_hi, 2);

    float* op = opart + (size_t)jq * OPF_SZ;
    float* lp = lpart + (size_t)jq * LPF_SZ;
    const int icol_lo = i0 + wm + gid, icol_hi = icol_lo + 8;
    if (tig == 0) {
        lp[(size_t)bh * HW + icol_lo] = l_lo;
        lp[(size_t)bh * HW + icol_hi] = l_hi;
    }
    #pragma unroll
    for (int nc = 0; nc < 8; nc++) {
        const int crow = b * CC + hd * DH + nc * 8 + 2 * tig;
        op[(size_t)crow * HW + icol_lo]       = oacc[nc][0];
        op[(size_t)(crow + 1) * HW + icol_lo] = oacc[nc][1];
        op[(size_t)crow * HW + icol_hi]       = oacc[nc][2];
        op[(size_t)(crow + 1) * HW + icol_hi] = oacc[nc][3];
    }
}

// ---------------------------------------------------------------------------
// Kernel 3b: combine split-KV partials (float4): ob = (sum O_q)/(sum l_q).
// ---------------------------------------------------------------------------
__global__ void comb_kernel(__nv_bfloat16* __restrict__ ob) {
    const int p = blockIdx.x * 256 + threadIdx.x;   // 4 els each
    const int i = (p & 1023) * 4;
    const int row = p >> 10;                        // b*256 + c
    const int bh = (row >> 8) * 4 + ((row & 255) >> 6);
    float4 o = make_float4(0.f, 0.f, 0.f, 0.f);
    float4 lv = make_float4(0.f, 0.f, 0.f, 0.f);
    #pragma unroll
    for (int qd = 0; qd < 4; qd++) {
        float4 t = *(const float4*)(g_opf + (size_t)qd * OPF_SZ + (size_t)row * HW + i);
        o.x += t.x; o.y += t.y; o.z += t.z; o.w += t.w;
        float4 lt = *(const float4*)(g_lpf + (size_t)qd * LPF_SZ + (size_t)bh * HW + i);
        lv.x += lt.x; lv.y += lt.y; lv.z += lt.z; lv.w += lt.w;
    }
    uint2 r;
    r.x = pk_bf16(o.x / lv.x, o.y / lv.y);
    r.y = pk_bf16(o.z / lv.z, o.w / lv.w);
    *(uint2*)(ob + (size_t)row * HW + i) = r;
}

// ---------------------------------------------------------------------------
extern "C" void kernel_launch(void* const* d_in, const int* in_sizes, int n_in,
                              void* d_out, int out_size) {
    (void)in_sizes; (void)n_in; (void)out_size;
    const float* x      = (const float*)d_in[0];
    const float* norm_w = (const float*)d_in[1];
    const float* norm_b = (const float*)d_in[2];
    const float* qkv_w  = (const float*)d_in[3];
    const float* qkv_b  = (const float*)d_in[4];
    const float* proj_w = (const float*)d_in[5];
    const float* proj_b = (const float*)d_in[6];
    float* out = (float*)d_out;

    __nv_bfloat16 *hb, *qkvh, *ob, *qwT, *pwT;
    float *opf, *lpf;
    cudaGetSymbolAddress((void**)&hb,    g_hb);
    cudaGetSymbolAddress((void**)&qkvh,  g_qkvh);
    cudaGetSymbolAddress((void**)&ob,    g_ob);
    cudaGetSymbolAddress((void**)&qwT,   g_qkvwT);
    cudaGetSymbolAddress((void**)&pwT,   g_projwT);
    cudaGetSymbolAddress((void**)&opf,   g_opf);
    cudaGetSymbolAddress((void**)&lpf,   g_lpf);

    cudaFuncSetAttribute(attn_kernel, cudaFuncAttributeMaxDynamicSharedMemorySize,
                         ATTN_SMEM_BYTES);
    cudaFuncSetAttribute(gemm_bf16_kernel, cudaFuncAttributeMaxDynamicSharedMemorySize,
                         GEMM_SMEM_BYTES);

    // 0) weight convert+transpose (bf16)
    wconv_kernel<<<768, 256>>>(qkv_w, proj_w);
    // 1) GroupNorm: partial sums, then apply -> bf16
    gn_part<<<256, 256>>>(x);
    gn_apply<<<512, 256>>>(x, norm_w, norm_b);
    // 2) qkv = qkv_w @ h + qkv_b -> Q,K bf16 / V fp16  (128m x 64n tiles)
    gemm_bf16_kernel<<<dim3(HW / 64, 768 / 128, BATCH), 256, GEMM_SMEM_BYTES>>>(
        qwT, hb, qkv_b, nullptr, nullptr, qkvh, 768, (long)CC * HW, (long)3 * CC * HW);
    // 3) attention, 4-way split-KV (fp16x2 softmax)
    attn_kernel<<<dim3(HW / 128, BATCH * NH, 4), 256, ATTN_SMEM_BYTES>>>(qkvh, opf, lpf);
    // 3b) combine partials -> bf16 O
    comb_kernel<<<(BATCH * CC * HW / 4) / 256, 256>>>(ob);
    // 4) out = proj_w @ o + proj_b + x  (f32, 128m x 64n tiles)
    gemm_bf16_kernel<<<dim3(HW / 64, CC / 128, BATCH), 256, GEMM_SMEM_BYTES>>>(
        pwT, ob, proj_b, x, out, nullptr, 256, (long)CC * HW, (long)CC * HW);
}